// round 5
// baseline (speedup 1.0000x reference)
#include <cuda_runtime.h>
#include <cuda_fp16.h>
#include <cstdint>
#include <cfloat>

#define W_TOTAL   262144
#define L_DIM     512
#define G_DIM     128
#define TILE_ROWS 64
#define NUM_TILES (W_TOTAL / TILE_ROWS)   // 4096
#define NKCH      8                       // K chunks of 64

// ---- smem layout (bytes), dynamic smem only ----
#define OFF_AH0    0                  // A fp16 [64][64], 8 KB
#define OFF_AH1    8192
#define OFF_B0     16384              // B fp16 [128n][64k], 16 KB
#define OFF_B1     32768              // GEMM region ends at 49152
#define OFF_SSC    0                  // epilogue reuse: float[64][132] = 33792
#define SSC_PITCH  132
#define OFF_SB     49152              // bias 128 f32
#define OFF_SPRE   49664              // tile prefix 128 f32
#define OFF_STATE  50176              // lookback state flag
#define SMEM_TOTAL 50192

// device globals (no runtime allocation allowed)
__device__ __half g_Wh[G_DIM * L_DIM];          // W1^T as fp16, [n][k] k-major
__device__ float  g_aggregate[NUM_TILES * G_DIM];
__device__ float  g_inclusive[NUM_TILES * G_DIM];
__device__ int    g_flags[NUM_TILES];

#define SW128(o) ((o) ^ (((o) >> 3) & 0x70))

// ---- PTX helpers ----
__device__ __forceinline__ uint32_t smem_u32(const void* p) {
    uint32_t a;
    asm("{ .reg .u64 t; cvta.to.shared.u64 t, %1; cvt.u32.u64 %0, t; }" : "=r"(a) : "l"(p));
    return a;
}
__device__ __forceinline__ void ldsm_x4(uint32_t& r0, uint32_t& r1, uint32_t& r2,
                                        uint32_t& r3, uint32_t addr) {
    asm volatile("ldmatrix.sync.aligned.m8n8.x4.shared.b16 {%0,%1,%2,%3}, [%4];"
                 : "=r"(r0), "=r"(r1), "=r"(r2), "=r"(r3) : "r"(addr));
}
__device__ __forceinline__ void mma_f16(float* c, const uint32_t* a, uint32_t b0, uint32_t b1) {
    asm volatile(
        "mma.sync.aligned.m16n8k16.row.col.f32.f16.f16.f32 "
        "{%0,%1,%2,%3}, {%4,%5,%6,%7}, {%8,%9}, {%0,%1,%2,%3};"
        : "+f"(c[0]), "+f"(c[1]), "+f"(c[2]), "+f"(c[3])
        : "r"(a[0]), "r"(a[1]), "r"(a[2]), "r"(a[3]), "r"(b0), "r"(b1));
}
__device__ __forceinline__ void cp_async16(uint32_t dst, const void* src) {
    asm volatile("cp.async.cg.shared.global [%0], [%1], 16;" :: "r"(dst), "l"(src));
}
#define CP_COMMIT() asm volatile("cp.async.commit_group;" ::: "memory")
#define CP_WAIT0()  asm volatile("cp.async.wait_group 0;" ::: "memory")

__device__ __forceinline__ int ld_flag_cg(const int* p) {
    int f; asm volatile("ld.global.cg.b32 %0, [%1];" : "=r"(f) : "l"(p)); return f;
}
__device__ __forceinline__ float ld_f_cg(const float* p) {
    float f; asm volatile("ld.global.cg.f32 %0, [%1];" : "=f"(f) : "l"(p)); return f;
}
__device__ __forceinline__ void st_cs4(float* p, float4 v) {
    asm volatile("st.global.cs.v4.f32 [%0], {%1,%2,%3,%4};"
                 :: "l"(p), "f"(v.x), "f"(v.y), "f"(v.z), "f"(v.w) : "memory");
}

// ---- merged prep kernel (1 launch): W1 -> fp16 transpose, zero flags ----
__global__ void prep_kernel(const float* __restrict__ W1) {   // W1: [512][128]
    int idx = blockIdx.x * 256 + threadIdx.x;                 // 65536
    int k = idx >> 7, n = idx & 127;
    g_Wh[n * L_DIM + k] = __float2half_rn(W1[idx]);
    if (idx < NUM_TILES) g_flags[idx] = 0;
}

// ---- main fused kernel: pipelined fp16 HMMA GEMM + cummax lookback ----
__global__ void __launch_bounds__(256, 3)
key_pool_mma(const float* __restrict__ A,      // [W, L]
             const float* __restrict__ gfeat,  // [G]
             const float* __restrict__ b1,     // [G]
             float* __restrict__ out, int write_tail) {
    extern __shared__ char sm[];
    const uint32_t smb = smem_u32(sm);
    float* Ssc   = (float*)(sm + OFF_SSC);
    float* Sb    = (float*)(sm + OFF_SB);
    float* Spre  = (float*)(sm + OFF_SPRE);
    int*   Sstat = (int*)(sm + OFF_STATE);

    const int tid  = threadIdx.x;
    const int wid  = tid >> 5;
    const int lane = tid & 31;
    const int tile = blockIdx.x;

    const int Rw = (wid & 3) * 16;   // warp row base (0..48)
    const int Cw = (wid >> 2) * 64;  // warp col base (0 or 64)

    const float4* A4 = (const float4*)(A + (size_t)tile * TILE_ROWS * L_DIM);

    float acc[8][4];
    #pragma unroll
    for (int n = 0; n < 8; ++n)
        #pragma unroll
        for (int j = 0; j < 4; ++j) acc[n][j] = 0.f;

    // ldmatrix per-thread offsets
    const int a_row  = (lane & 15);
    const int a_kb   = (lane >> 4) << 4;
    const int b_nrow = ((lane >> 4) & 1) * 8 + (lane & 7);
    const int b_kb   = ((lane >> 3) & 1) << 4;

    // ---- prologue: LDG A(0) into regs, cp.async B(0) ----
    float4 ra[4];
    #pragma unroll
    for (int i = 0; i < 4; ++i) {
        int e = tid + i * 256, r = e >> 4, q = e & 15;   // 1024 float4: [64 rows][16 q]
        ra[i] = __ldg(&A4[r * 128 + q]);
    }
    {
        const __half* Wh = g_Wh;
        #pragma unroll
        for (int i = 0; i < 4; ++i) {
            int e = tid + i * 256, n = e >> 3, u = e & 7;
            cp_async16(smb + OFF_B0 + SW128((uint32_t)(n * 128 + u * 16)),
                       Wh + n * L_DIM + u * 8);
        }
        CP_COMMIT();
    }

    // ---- pipelined mainloop: one __syncthreads per chunk ----
    #pragma unroll
    for (int kc = 0; kc < NKCH; ++kc) {
        char* ahp = sm + ((kc & 1) ? OFF_AH1 : OFF_AH0);
        const uint32_t ahb = smb + ((kc & 1) ? OFF_AH1 : OFF_AH0);
        const uint32_t bbb = smb + ((kc & 1) ? OFF_B1 : OFF_B0);

        // convert + STS A(kc) from regs
        #pragma unroll
        for (int i = 0; i < 4; ++i) {
            int e = tid + i * 256, r = e >> 4, q = e & 15;
            __half2 h01 = __float22half2_rn(make_float2(ra[i].x, ra[i].y));
            __half2 h23 = __float22half2_rn(make_float2(ra[i].z, ra[i].w));
            *(uint2*)(ahp + SW128((uint32_t)(r * 128 + q * 8))) =
                make_uint2(*(uint32_t*)&h01, *(uint32_t*)&h23);
        }
        // prefetch A(kc+1) into the same regs
        if (kc < NKCH - 1) {
            #pragma unroll
            for (int i = 0; i < 4; ++i) {
                int e = tid + i * 256, r = e >> 4, q = e & 15;
                ra[i] = __ldg(&A4[r * 128 + (kc + 1) * 16 + q]);
            }
        }

        CP_WAIT0();          // B(kc) landed
        __syncthreads();     // all staged; MMA(kc-1) complete

        // prefetch B(kc+1) into the other buffer
        if (kc < NKCH - 1) {
            const uint32_t bnext = smb + (((kc + 1) & 1) ? OFF_B1 : OFF_B0);
            const __half* Wh = g_Wh;
            #pragma unroll
            for (int i = 0; i < 4; ++i) {
                int e = tid + i * 256, n = e >> 3, u = e & 7;
                cp_async16(bnext + SW128((uint32_t)(n * 128 + u * 16)),
                           Wh + n * L_DIM + (kc + 1) * 64 + u * 8);
            }
            CP_COMMIT();
        }

        // ---- MMA over 4 k16 steps ----
        #pragma unroll
        for (int k16 = 0; k16 < 4; ++k16) {
            const int kstep = k16 * 32;
            uint32_t ah[4];
            {
                uint32_t offA = (uint32_t)((Rw + a_row) * 128 + kstep + a_kb);
                ldsm_x4(ah[0], ah[1], ah[2], ah[3], ahb + SW128(offA));
            }
            #pragma unroll
            for (int nt2 = 0; nt2 < 4; ++nt2) {
                uint32_t offB = (uint32_t)((Cw + nt2 * 16 + b_nrow) * 128 + kstep + b_kb);
                uint32_t bf[4];
                ldsm_x4(bf[0], bf[1], bf[2], bf[3], bbb + SW128(offB));
                mma_f16(acc[nt2 * 2 + 0], ah, bf[0], bf[1]);
                mma_f16(acc[nt2 * 2 + 1], ah, bf[2], bf[3]);
            }
        }
    }

    // ---- epilogue: bias + dump into smem [64][SSC_PITCH] ----
    if (tid < G_DIM) Sb[tid] = __ldg(&b1[tid]);
    __syncthreads();     // all LDSM/MMA done before Ssc overwrites GEMM smem

    const int g  = lane >> 2;
    const int cq = (lane & 3) * 2;
    #pragma unroll
    for (int nt = 0; nt < 8; ++nt) {
        int col = Cw + nt * 8 + cq;
        float2 b2 = *(float2*)&Sb[col];
        int r0 = Rw + g;
        *(float2*)&Ssc[r0 * SSC_PITCH + col] =
            make_float2(acc[nt][0] + b2.x, acc[nt][1] + b2.y);
        *(float2*)&Ssc[(r0 + 8) * SSC_PITCH + col] =
            make_float2(acc[nt][2] + b2.x, acc[nt][3] + b2.y);
    }
    __syncthreads();

    // ---- column cummax over 64 rows: warp w handles 16 columns ----
    {
        const int cw = wid * 16;
        float carry[16];
        #pragma unroll
        for (int j = 0; j < 16; ++j) carry[j] = -FLT_MAX;
        #pragma unroll
        for (int rb = 0; rb < 2; ++rb) {
            int row = rb * 32 + lane;
            float v[16];
            #pragma unroll
            for (int q = 0; q < 4; ++q) {
                float4 x = *(float4*)&Ssc[row * SSC_PITCH + cw + q * 4];
                v[q * 4 + 0] = x.x; v[q * 4 + 1] = x.y;
                v[q * 4 + 2] = x.z; v[q * 4 + 3] = x.w;
            }
            #pragma unroll
            for (int d = 1; d < 32; d <<= 1) {
                #pragma unroll
                for (int j = 0; j < 16; ++j) {
                    float tshf = __shfl_up_sync(0xffffffffu, v[j], d);
                    if (lane >= d) v[j] = fmaxf(v[j], tshf);
                }
            }
            #pragma unroll
            for (int j = 0; j < 16; ++j) v[j] = fmaxf(v[j], carry[j]);
            #pragma unroll
            for (int q = 0; q < 4; ++q) {
                float4 x = make_float4(v[q * 4], v[q * 4 + 1], v[q * 4 + 2], v[q * 4 + 3]);
                *(float4*)&Ssc[row * SSC_PITCH + cw + q * 4] = x;
            }
            #pragma unroll
            for (int j = 0; j < 16; ++j) carry[j] = __shfl_sync(0xffffffffu, v[j], 31);
        }
    }
    __syncthreads();

    // ---- decoupled lookback over tiles ----
    float incl = -FLT_MAX;
    if (tile == 0) {
        if (tid < G_DIM) {
            float a = Ssc[(TILE_ROWS - 1) * SSC_PITCH + tid];
            float run = __ldg(&gfeat[tid]);       // seed with global feature
            incl = fmaxf(a, run);
            g_inclusive[tid] = incl;
            Spre[tid] = run;
        }
        __threadfence();
        __syncthreads();
        if (tid == 0) atomicExch(&g_flags[0], 2);
    } else {
        float a = -FLT_MAX;
        if (tid < G_DIM) {
            a = Ssc[(TILE_ROWS - 1) * SSC_PITCH + tid];
            g_aggregate[(size_t)tile * G_DIM + tid] = a;
        }
        __threadfence();
        __syncthreads();
        if (tid == 0) atomicExch(&g_flags[tile], 1);

        float run = -FLT_MAX;
        int p = tile - 1;
        while (true) {
            if (tid == 0) {
                int f = ld_flag_cg(&g_flags[p]);
                while (f == 0) { __nanosleep(50); f = ld_flag_cg(&g_flags[p]); }
                *Sstat = f;
            }
            __syncthreads();
            int f = *Sstat;
            if (tid < G_DIM) {
                const float* src = (f == 2) ? &g_inclusive[(size_t)p * G_DIM]
                                            : &g_aggregate[(size_t)p * G_DIM];
                run = fmaxf(run, ld_f_cg(&src[tid]));
            }
            __syncthreads();
            if (f == 2) break;
            --p;
        }
        if (tid < G_DIM) {
            incl = fmaxf(run, a);
            g_inclusive[(size_t)tile * G_DIM + tid] = incl;
            Spre[tid] = run;
        }
        __threadfence();
        __syncthreads();
        if (tid == 0) atomicExch(&g_flags[tile], 2);
    }
    __syncthreads();

    // ---- combine with tile prefix, stream out (.cs: keep B L2-resident) ----
    float* outp = out + (size_t)tile * TILE_ROWS * G_DIM;
    #pragma unroll
    for (int i = 0; i < 8; ++i) {
        int e = tid + i * 256;                    // 0..2047 float4
        int r = e >> 5, c4 = e & 31;
        const float* s  = &Ssc[r * SSC_PITCH + c4 * 4];
        const float* pp = &Spre[c4 * 4];
        float4 o;
        o.x = fmaxf(s[0], pp[0]);
        o.y = fmaxf(s[1], pp[1]);
        o.z = fmaxf(s[2], pp[2]);
        o.w = fmaxf(s[3], pp[3]);
        st_cs4(&outp[e * 4], o);
    }
    if (write_tail && tile == NUM_TILES - 1 && tid < G_DIM)
        out[(size_t)W_TOTAL * G_DIM + tid] = incl;
}

extern "C" void kernel_launch(void* const* d_in, const int* in_sizes, int n_in,
                              void* d_out, int out_size) {
    const float* local = (const float*)d_in[0];  // [262144, 512]
    const float* gfeat = (const float*)d_in[1];  // [1, 128]
    const float* W1    = (const float*)d_in[2];  // [512, 128]
    const float* b1    = (const float*)d_in[3];  // [128]
    float* out = (float*)d_out;

    static int configured = 0;
    if (!configured) {
        cudaFuncSetAttribute(key_pool_mma,
                             cudaFuncAttributeMaxDynamicSharedMemorySize, SMEM_TOTAL);
        configured = 1;
    }
    int write_tail = (out_size >= W_TOTAL * G_DIM + G_DIM) ? 1 : 0;

    prep_kernel<<<256, 256>>>(W1);
    key_pool_mma<<<NUM_TILES, 256, SMEM_TOTAL>>>(local, gfeat, b1, out, write_tail);
}

// round 6
// speedup vs baseline: 1.3047x; 1.3047x over previous
#include <cuda_runtime.h>
#include <cuda_fp16.h>
#include <cstdint>
#include <cfloat>

#define W_TOTAL   262144
#define L_DIM     512
#define G_DIM     128
#define TILE_ROWS 128
#define NUM_TILES (W_TOTAL / TILE_ROWS)   // 2048
#define NKCH      8                       // K chunks of 64

// ---- smem layout (bytes), dynamic smem only ----
#define OFF_AH0    0                  // A fp16 [128][64], 16 KB
#define OFF_AH1    16384
#define OFF_B0     32768              // B fp16 [128n][64k], 16 KB
#define OFF_B1     49152              // GEMM region ends at 65536
#define OFF_SSC    0                  // epilogue reuse: float[128][132]
#define SSC_PITCH  132
#define OFF_SB     67584              // bias 128 f32
#define OFF_SPRE   68096              // tile prefix 128 f32
#define OFF_STATE  68608              // lookback window state (int)
#define SMEM_TOTAL 68640

// device globals (no runtime allocation allowed)
__device__ __half g_Wh[G_DIM * L_DIM];          // W1^T as fp16, [n][k] k-major
__device__ float  g_aggregate[NUM_TILES * G_DIM];
__device__ float  g_inclusive[NUM_TILES * G_DIM];
__device__ int    g_flags[NUM_TILES];

#define SW128(o) ((o) ^ (((o) >> 3) & 0x70))

// ---- PTX helpers ----
__device__ __forceinline__ uint32_t smem_u32(const void* p) {
    uint32_t a;
    asm("{ .reg .u64 t; cvta.to.shared.u64 t, %1; cvt.u32.u64 %0, t; }" : "=r"(a) : "l"(p));
    return a;
}
__device__ __forceinline__ void ldsm_x4(uint32_t& r0, uint32_t& r1, uint32_t& r2,
                                        uint32_t& r3, uint32_t addr) {
    asm volatile("ldmatrix.sync.aligned.m8n8.x4.shared.b16 {%0,%1,%2,%3}, [%4];"
                 : "=r"(r0), "=r"(r1), "=r"(r2), "=r"(r3) : "r"(addr));
}
__device__ __forceinline__ void mma_f16(float* c, const uint32_t* a, uint32_t b0, uint32_t b1) {
    asm volatile(
        "mma.sync.aligned.m16n8k16.row.col.f32.f16.f16.f32 "
        "{%0,%1,%2,%3}, {%4,%5,%6,%7}, {%8,%9}, {%0,%1,%2,%3};"
        : "+f"(c[0]), "+f"(c[1]), "+f"(c[2]), "+f"(c[3])
        : "r"(a[0]), "r"(a[1]), "r"(a[2]), "r"(a[3]), "r"(b0), "r"(b1));
}
__device__ __forceinline__ void cp_async16(uint32_t dst, const void* src) {
    asm volatile("cp.async.cg.shared.global [%0], [%1], 16;" :: "r"(dst), "l"(src));
}
#define CP_COMMIT() asm volatile("cp.async.commit_group;" ::: "memory")
#define CP_WAIT0()  asm volatile("cp.async.wait_group 0;" ::: "memory")

__device__ __forceinline__ int ld_flag_cg(const int* p) {
    int f; asm volatile("ld.global.cg.b32 %0, [%1];" : "=r"(f) : "l"(p)); return f;
}
__device__ __forceinline__ float ld_f_cg(const float* p) {
    float f; asm volatile("ld.global.cg.f32 %0, [%1];" : "=f"(f) : "l"(p)); return f;
}
__device__ __forceinline__ void st_cs4(float* p, float4 v) {
    asm volatile("st.global.cs.v4.f32 [%0], {%1,%2,%3,%4};"
                 :: "l"(p), "f"(v.x), "f"(v.y), "f"(v.z), "f"(v.w) : "memory");
}

// ---- merged prep kernel (1 launch): W1 -> fp16 transpose, zero flags ----
__global__ void prep_kernel(const float* __restrict__ W1) {   // W1: [512][128]
    int idx = blockIdx.x * 256 + threadIdx.x;                 // 65536
    int k = idx >> 7, n = idx & 127;
    g_Wh[n * L_DIM + k] = __float2half_rn(W1[idx]);
    if (idx < NUM_TILES) g_flags[idx] = 0;
}

// ---- main fused kernel: pipelined fp16 HMMA GEMM + cummax lookback ----
__global__ void __launch_bounds__(256, 2)
key_pool_mma(const float* __restrict__ A,      // [W, L]
             const float* __restrict__ gfeat,  // [G]
             const float* __restrict__ b1,     // [G]
             float* __restrict__ out, int write_tail) {
    extern __shared__ char sm[];
    const uint32_t smb = smem_u32(sm);
    float* Ssc   = (float*)(sm + OFF_SSC);
    float* Sb    = (float*)(sm + OFF_SB);
    float* Spre  = (float*)(sm + OFF_SPRE);
    int*   Sstat = (int*)(sm + OFF_STATE);

    const int tid  = threadIdx.x;
    const int wid  = tid >> 5;
    const int lane = tid & 31;
    const int tile = blockIdx.x;

    const int Rw = (wid & 3) * 32;   // warp row base
    const int Cw = (wid >> 2) * 64;  // warp col base

    const float4* A4 = (const float4*)(A + (size_t)tile * TILE_ROWS * L_DIM);

    float acc[2][8][4];
    #pragma unroll
    for (int t = 0; t < 2; ++t)
        #pragma unroll
        for (int n = 0; n < 8; ++n)
            #pragma unroll
            for (int j = 0; j < 4; ++j) acc[t][n][j] = 0.f;

    // ldmatrix per-thread offsets
    const int a_row  = (lane & 15);
    const int a_kb   = (lane >> 4) << 4;
    const int b_nrow = ((lane >> 4) & 1) * 8 + (lane & 7);
    const int b_kb   = ((lane >> 3) & 1) << 4;

    // ---- prologue: LDG A(0) into regs, cp.async B(0) ----
    float4 ra[8];
    #pragma unroll
    for (int i = 0; i < 8; ++i) {
        int e = tid + i * 256, r = e >> 4, q = e & 15;
        ra[i] = __ldg(&A4[r * 128 + q]);
    }
    {
        const __half* Wh = g_Wh;
        #pragma unroll
        for (int i = 0; i < 4; ++i) {
            int e = tid + i * 256, n = e >> 3, u = e & 7;
            cp_async16(smb + OFF_B0 + SW128((uint32_t)(n * 128 + u * 16)),
                       Wh + n * L_DIM + u * 8);
        }
        CP_COMMIT();
    }

    // ---- pipelined mainloop: one __syncthreads per chunk ----
    #pragma unroll
    for (int kc = 0; kc < NKCH; ++kc) {
        char* ahp = sm + ((kc & 1) ? OFF_AH1 : OFF_AH0);
        const uint32_t ahb = smb + ((kc & 1) ? OFF_AH1 : OFF_AH0);
        const uint32_t bbb = smb + ((kc & 1) ? OFF_B1 : OFF_B0);

        // convert + STS A(kc) from regs
        #pragma unroll
        for (int i = 0; i < 8; ++i) {
            int e = tid + i * 256, r = e >> 4, q = e & 15;
            __half2 h01 = __float22half2_rn(make_float2(ra[i].x, ra[i].y));
            __half2 h23 = __float22half2_rn(make_float2(ra[i].z, ra[i].w));
            *(uint2*)(ahp + SW128((uint32_t)(r * 128 + q * 8))) =
                make_uint2(*(uint32_t*)&h01, *(uint32_t*)&h23);
        }
        // prefetch A(kc+1) into the same regs
        if (kc < NKCH - 1) {
            #pragma unroll
            for (int i = 0; i < 8; ++i) {
                int e = tid + i * 256, r = e >> 4, q = e & 15;
                ra[i] = __ldg(&A4[r * 128 + (kc + 1) * 16 + q]);
            }
        }

        CP_WAIT0();          // B(kc) landed
        __syncthreads();     // all staged; MMA(kc-1) complete

        // prefetch B(kc+1) into the other buffer
        if (kc < NKCH - 1) {
            const uint32_t bnext = smb + (((kc + 1) & 1) ? OFF_B1 : OFF_B0);
            const __half* Wh = g_Wh;
            #pragma unroll
            for (int i = 0; i < 4; ++i) {
                int e = tid + i * 256, n = e >> 3, u = e & 7;
                cp_async16(bnext + SW128((uint32_t)(n * 128 + u * 16)),
                           Wh + n * L_DIM + (kc + 1) * 64 + u * 8);
            }
            CP_COMMIT();
        }

        // ---- MMA over 4 k16 steps ----
        #pragma unroll
        for (int k16 = 0; k16 < 4; ++k16) {
            const int kstep = k16 * 32;
            uint32_t ah[2][4];
            #pragma unroll
            for (int t = 0; t < 2; ++t) {
                uint32_t offA = (uint32_t)((Rw + t * 16 + a_row) * 128 + kstep + a_kb);
                ldsm_x4(ah[t][0], ah[t][1], ah[t][2], ah[t][3], ahb + SW128(offA));
            }
            #pragma unroll
            for (int nt2 = 0; nt2 < 4; ++nt2) {
                uint32_t offB = (uint32_t)((Cw + nt2 * 16 + b_nrow) * 128 + kstep + b_kb);
                uint32_t bf[4];
                ldsm_x4(bf[0], bf[1], bf[2], bf[3], bbb + SW128(offB));
                #pragma unroll
                for (int half = 0; half < 2; ++half) {
                    const int nt = nt2 * 2 + half;
                    #pragma unroll
                    for (int t = 0; t < 2; ++t)
                        mma_f16(acc[t][nt], ah[t], bf[half * 2], bf[half * 2 + 1]);
                }
            }
        }
    }

    // ---- epilogue: bias + dump into smem [128][SSC_PITCH] ----
    if (tid < G_DIM) Sb[tid] = __ldg(&b1[tid]);
    __syncthreads();     // MMA(7) done before Ssc overwrites GEMM smem

    const int g  = lane >> 2;
    const int cq = (lane & 3) * 2;
    #pragma unroll
    for (int t = 0; t < 2; ++t) {
        #pragma unroll
        for (int nt = 0; nt < 8; ++nt) {
            int col = Cw + nt * 8 + cq;
            float2 b2 = *(float2*)&Sb[col];
            int r0 = Rw + t * 16 + g;
            *(float2*)&Ssc[r0 * SSC_PITCH + col] =
                make_float2(acc[t][nt][0] + b2.x, acc[t][nt][1] + b2.y);
            *(float2*)&Ssc[(r0 + 8) * SSC_PITCH + col] =
                make_float2(acc[t][nt][2] + b2.x, acc[t][nt][3] + b2.y);
        }
    }
    __syncthreads();

    // ---- column cummax over 128 rows: warp w handles 16 columns ----
    {
        const int cw = wid * 16;
        float carry[16];
        #pragma unroll
        for (int j = 0; j < 16; ++j) carry[j] = -FLT_MAX;
        for (int rb = 0; rb < 4; ++rb) {
            int row = rb * 32 + lane;
            float v[16];
            #pragma unroll
            for (int q = 0; q < 4; ++q) {
                float4 x = *(float4*)&Ssc[row * SSC_PITCH + cw + q * 4];
                v[q * 4 + 0] = x.x; v[q * 4 + 1] = x.y;
                v[q * 4 + 2] = x.z; v[q * 4 + 3] = x.w;
            }
            #pragma unroll
            for (int d = 1; d < 32; d <<= 1) {
                #pragma unroll
                for (int j = 0; j < 16; ++j) {
                    float tshf = __shfl_up_sync(0xffffffffu, v[j], d);
                    if (lane >= d) v[j] = fmaxf(v[j], tshf);
                }
            }
            #pragma unroll
            for (int j = 0; j < 16; ++j) v[j] = fmaxf(v[j], carry[j]);
            #pragma unroll
            for (int q = 0; q < 4; ++q) {
                float4 x = make_float4(v[q * 4], v[q * 4 + 1], v[q * 4 + 2], v[q * 4 + 3]);
                *(float4*)&Ssc[row * SSC_PITCH + cw + q * 4] = x;
            }
            #pragma unroll
            for (int j = 0; j < 16; ++j) carry[j] = __shfl_sync(0xffffffffu, v[j], 31);
        }
    }
    __syncthreads();

    // ---- decoupled lookback over tiles (32-wide parallel window) ----
    float incl = -FLT_MAX;
    if (tile == 0) {
        if (tid < G_DIM) {
            float a = Ssc[127 * SSC_PITCH + tid];
            float run = __ldg(&gfeat[tid]);       // seed with global feature
            incl = fmaxf(a, run);
            g_inclusive[tid] = incl;
            Spre[tid] = run;
        }
        __threadfence();
        __syncthreads();
        if (tid == 0) atomicExch(&g_flags[0], 2);
    } else {
        float a = -FLT_MAX;
        if (tid < G_DIM) {
            a = Ssc[127 * SSC_PITCH + tid];
            g_aggregate[(size_t)tile * G_DIM + tid] = a;
        }
        __threadfence();
        __syncthreads();
        if (tid == 0) atomicExch(&g_flags[tile], 1);

        float run = -FLT_MAX;
        int p = tile - 1;
        while (true) {
            // warp 0: poll window [p-31 .. p], lane l watches flag[p-l]
            if (wid == 0) {
                int idx = p - lane;
                int f = 1;                         // idx<0: dummy "aggregate"
                if (idx >= 0) {
                    f = ld_flag_cg(&g_flags[idx]);
                    while (f == 0) { __nanosleep(32); f = ld_flag_cg(&g_flags[idx]); }
                }
                unsigned ball = __ballot_sync(0xffffffffu, f == 2);
                if (lane == 0)
                    Sstat[0] = (ball == 0) ? 32 : (__ffs(ball) - 1); // nearest inclusive
            }
            __syncthreads();
            int l2 = Sstat[0];
            int lstop = (l2 < 32) ? l2 : 31;
            if (tid < G_DIM) {
                // up to 32 independent loads, combine is order-free (max)
                for (int l = 0; l <= lstop; ++l) {
                    int idx = p - l;
                    const float* src = (l == l2) ? &g_inclusive[(size_t)idx * G_DIM]
                                                 : &g_aggregate[(size_t)idx * G_DIM];
                    run = fmaxf(run, ld_f_cg(&src[tid]));
                }
            }
            __syncthreads();                       // protect Sstat reuse
            if (l2 < 32) break;
            p -= 32;
        }
        if (tid < G_DIM) {
            incl = fmaxf(run, a);
            g_inclusive[(size_t)tile * G_DIM + tid] = incl;
            Spre[tid] = run;
        }
        __threadfence();
        __syncthreads();
        if (tid == 0) atomicExch(&g_flags[tile], 2);
    }
    __syncthreads();

    // ---- combine with tile prefix, stream out (.cs keeps W L2-resident) ----
    float* outp = out + (size_t)tile * TILE_ROWS * G_DIM;
    #pragma unroll
    for (int i = 0; i < 16; ++i) {
        int e = tid + i * 256;                    // 0..4095 float4
        int r = e >> 5, c4 = e & 31;
        const float* s  = &Ssc[r * SSC_PITCH + c4 * 4];
        const float* pp = &Spre[c4 * 4];
        float4 o;
        o.x = fmaxf(s[0], pp[0]);
        o.y = fmaxf(s[1], pp[1]);
        o.z = fmaxf(s[2], pp[2]);
        o.w = fmaxf(s[3], pp[3]);
        st_cs4(&outp[e * 4], o);
    }
    if (write_tail && tile == NUM_TILES - 1 && tid < G_DIM)
        out[(size_t)W_TOTAL * G_DIM + tid] = incl;
}

extern "C" void kernel_launch(void* const* d_in, const int* in_sizes, int n_in,
                              void* d_out, int out_size) {
    const float* local = (const float*)d_in[0];  // [262144, 512]
    const float* gfeat = (const float*)d_in[1];  // [1, 128]
    const float* W1    = (const float*)d_in[2];  // [512, 128]
    const float* b1    = (const float*)d_in[3];  // [128]
    float* out = (float*)d_out;

    static int configured = 0;
    if (!configured) {
        cudaFuncSetAttribute(key_pool_mma,
                             cudaFuncAttributeMaxDynamicSharedMemorySize, SMEM_TOTAL);
        configured = 1;
    }
    int write_tail = (out_size >= W_TOTAL * G_DIM + G_DIM) ? 1 : 0;

    prep_kernel<<<256, 256>>>(W1);
    key_pool_mma<<<NUM_TILES, 256, SMEM_TOTAL>>>(local, gfeat, b1, out, write_tail);
}